// round 13
// baseline (speedup 1.0000x reference)
#include <cuda_runtime.h>
#include <math.h>

#define Nn 16384
#define Ee 262144
#define Tt 4
#define Dd 64
#define TND (Tt*Nn*Dd)

// ---- scratch (zero-initialized at module load; fused1 re-zeros deg/flags each run) ----
__device__ int   g_rr[Ee];            // packed (row | rank<<14)
__device__ int   g_cet[Ee];           // raw packed (col | ty<<14)
__device__ int   g_ect[Ee];           // CSR-sorted packed
__device__ int   g_deg[Nn], g_off[Nn + 1];
__device__ int   g_bval[16], g_bflag[16];
__device__ float g_hw0[Nn * Dd];      // x @ we0 (single plane)
__device__ float g_hw1[TND];          // h1 @ we1, INTERLEAVED [n][t][d]
__device__ float g_sj0[Nn * Tt];      // interleaved [n][t]
__device__ float g_sj1[Nn * Tt];
__device__ float g_rg[2][Tt * Tt];
__device__ float g_vg[2][Tt * Dd];

// ---- hist: per-thread dtype detect + degree count (rank makes scatter atomic-free) ----
__global__ void k_hist(const void* __restrict__ eidx, const void* __restrict__ etyp) {
    int i = blockIdx.x * blockDim.x + threadIdx.x;   // Ee/4 threads
    const long long* p = (const long long*)eidx;
    // int64-interpreted reads of this thread's 4 row entries (in-bounds for both dtypes)
    long long d0 = p[4 * i], d1 = p[4 * i + 1], d2 = p[4 * i + 2], d3 = p[4 * i + 3];
    bool is64 = ((unsigned long long)(d0 | d1 | d2 | d3)) < (unsigned long long)Nn;
    int4 rv, cv, tv;
    if (is64) {
        const long long* q = (const long long*)etyp;
        rv = make_int4((int)d0, (int)d1, (int)d2, (int)d3);
        int e = i * 4;
        cv = make_int4((int)p[Ee + e], (int)p[Ee + e + 1], (int)p[Ee + e + 2], (int)p[Ee + e + 3]);
        tv = make_int4((int)q[e], (int)q[e + 1], (int)q[e + 2], (int)q[e + 3]);
    } else {
        rv = ((const int4*)eidx)[i];
        cv = ((const int4*)eidx)[Ee / 4 + i];
        tv = ((const int4*)etyp)[i];
    }
    int4 rr, ce;
    rr.x = rv.x | (atomicAdd(&g_deg[rv.x], 1) << 14);
    rr.y = rv.y | (atomicAdd(&g_deg[rv.y], 1) << 14);
    rr.z = rv.z | (atomicAdd(&g_deg[rv.z], 1) << 14);
    rr.w = rv.w | (atomicAdd(&g_deg[rv.w], 1) << 14);
    ce.x = cv.x | (tv.x << 14);
    ce.y = cv.y | (tv.y << 14);
    ce.z = cv.z | (tv.z << 14);
    ce.w = cv.w | (tv.w << 14);
    ((int4*)g_rr)[i]  = rr;
    ((int4*)g_cet)[i] = ce;
}

// ---- rgef for BOTH layers ----
__device__ void rgef_body(const float* __restrict__ ef0, const float* __restrict__ theta,
                          const float* __restrict__ wr) {
    __shared__ float efa[Tt * Dd], efb[Tt * Dd];
    int tid = threadIdx.x;              // 256
    int t = tid >> 6, d = tid & 63;
    efa[tid] = ef0[tid];
    __syncthreads();
    if (tid < Tt * Tt) {
        int t1 = tid >> 2, t2 = tid & 3;
        const float* tg = theta + t1 * 3 * Dd;
        float s = 0.f;
#pragma unroll
        for (int k = 0; k < Dd; k++) s += tg[k] * efa[t2 * Dd + k];
        g_rg[0][tid] = s;
    }
    {
        float s = 0.f;
#pragma unroll
        for (int k = 0; k < Dd; k++) s += efa[t * Dd + k] * wr[k * Dd + d];
        g_vg[0][tid] = 1.f / (1.f + __expf(-s));
        efb[tid] = fmaxf(s, 0.f);
    }
    __syncthreads();
    if (tid < Tt * Tt) {
        int t1 = tid >> 2, t2 = tid & 3;
        const float* tg = theta + (Tt * 3 * Dd) + t1 * 3 * Dd;
        float s = 0.f;
#pragma unroll
        for (int k = 0; k < Dd; k++) s += tg[k] * efb[t2 * Dd + k];
        g_rg[1][tid] = s;
    }
    {
        const float* w1 = wr + Dd * Dd;
        float s = 0.f;
#pragma unroll
        for (int k = 0; k < Dd; k++) s += efb[t * Dd + k] * w1[k * Dd + d];
        g_vg[1][tid] = 1.f / (1.f + __expf(-s));
    }
}

// ---- scan body: 256 threads x int4, decoupled lookback (blocks 0..15) ----
__device__ void scan_body(int b) {
    __shared__ int sh[256];
    __shared__ int base_s;
    int tid = threadIdx.x;
    int i4 = b * 256 + tid;
    int4 v = ((const int4*)g_deg)[i4];
    int lsum = v.x + v.y + v.z + v.w;
    sh[tid] = lsum;
    __syncthreads();
    for (int off = 1; off < 256; off <<= 1) {
        int u = (tid >= off) ? sh[tid - off] : 0;
        __syncthreads();
        sh[tid] += u;
        __syncthreads();
    }
    if (tid == 255) {
        g_bval[b] = sh[255];
        __threadfence();
        atomicExch(&g_bflag[b], 1);
    }
    if (tid == 0) {
        int acc = 0;
        for (int j = 0; j < b; j++) {
            while (atomicAdd(&g_bflag[j], 0) == 0) { }
            acc += g_bval[j];
        }
        base_s = acc;
    }
    __syncthreads();
    int o = base_s + sh[tid] - lsum;
    int4 off4;
    off4.x = o;
    off4.y = o + v.x;
    off4.z = o + v.x + v.y;
    off4.w = o + v.x + v.y + v.z;
    ((int4*)g_off)[i4] = off4;
    if (b == 15 && tid == 255) g_off[Nn] = Ee;
}

// ---- gemm0 body: hw0 = x @ we0 + sj0 (blocks 17..) ----
__device__ void gemm0_body(int blk, const float* __restrict__ x,
                           const float* __restrict__ we, const float* __restrict__ theta) {
    __shared__ float we_s[Dd * Dd];
    __shared__ float h_s[32 * Dd];
    __shared__ float thj_s[Tt * Dd];
    int tid = threadIdx.x;              // 256
    int n0 = blk * 32;
#pragma unroll
    for (int i = 0; i < 16; i++) we_s[tid + i * 256] = we[tid + i * 256];
    const float* hb = x + (size_t)n0 * Dd;
#pragma unroll
    for (int i = 0; i < 8; i++) h_s[tid + i * 256] = hb[tid + i * 256];
    {
        int t = tid >> 6, d = tid & 63;
        thj_s[t * Dd + d] = theta[t * 3 * Dd + 2 * Dd + d];
    }
    __syncthreads();
    int d = tid & 63, ng = tid >> 6;
    float acc[8] = {0.f, 0.f, 0.f, 0.f, 0.f, 0.f, 0.f, 0.f};
#pragma unroll
    for (int k = 0; k < Dd; k++) {
        float wv = we_s[k * Dd + d];
#pragma unroll
        for (int j = 0; j < 8; j++) acc[j] += h_s[(ng * 8 + j) * Dd + k] * wv;
    }
    float* ob = g_hw0 + (size_t)n0 * Dd;
#pragma unroll
    for (int j = 0; j < 8; j++) ob[(ng * 8 + j) * Dd + d] = acc[j];

    int wid = tid >> 5, lane = tid & 31;
#pragma unroll
    for (int j = 0; j < 4; j++) {
        int nl = wid * 4 + j;
        float a = h_s[nl * Dd + lane], b = h_s[nl * Dd + lane + 32];
#pragma unroll
        for (int t = 0; t < Tt; t++) {
            float sj = a * thj_s[t * Dd + lane] + b * thj_s[t * Dd + lane + 32];
#pragma unroll
            for (int o = 16; o; o >>= 1) sj += __shfl_down_sync(0xffffffffu, sj, o);
            if (lane == 0) g_sj0[(n0 + nl) * Tt + t] = sj;
        }
    }
}

// ---- mid: scan (0..15) | rgef (16) | gemm0 (17..), all independent ----
__global__ void k_mid(const float* __restrict__ x, const float* __restrict__ ef0,
                      const float* __restrict__ we, const float* __restrict__ theta,
                      const float* __restrict__ wr) {
    int b = blockIdx.x;
    if (b < 16) { scan_body(b); return; }
    if (b == 16) { rgef_body(ef0, theta, wr); return; }
    gemm0_body(b - 17, x, we, theta);
}

// ---- scatter: atomic-free, 8 edges/thread for MLP ----
__global__ void k_scatter() {
    int i = blockIdx.x * blockDim.x + threadIdx.x;   // Ee/8 threads
    int4 r0 = ((const int4*)g_rr)[2 * i];
    int4 r1 = ((const int4*)g_rr)[2 * i + 1];
    int4 c0 = ((const int4*)g_cet)[2 * i];
    int4 c1 = ((const int4*)g_cet)[2 * i + 1];
    int p0 = g_off[r0.x & 16383] + (((unsigned)r0.x) >> 14);
    int p1 = g_off[r0.y & 16383] + (((unsigned)r0.y) >> 14);
    int p2 = g_off[r0.z & 16383] + (((unsigned)r0.z) >> 14);
    int p3 = g_off[r0.w & 16383] + (((unsigned)r0.w) >> 14);
    int p4 = g_off[r1.x & 16383] + (((unsigned)r1.x) >> 14);
    int p5 = g_off[r1.y & 16383] + (((unsigned)r1.y) >> 14);
    int p6 = g_off[r1.z & 16383] + (((unsigned)r1.z) >> 14);
    int p7 = g_off[r1.w & 16383] + (((unsigned)r1.w) >> 14);
    g_ect[p0] = c0.x; g_ect[p1] = c0.y; g_ect[p2] = c0.z; g_ect[p3] = c0.w;
    g_ect[p4] = c1.x; g_ect[p5] = c1.y; g_ect[p6] = c1.z; g_ect[p7] = c1.w;
}

// ---- fused layer 0: warp per NODE, float2 lanes, pk double-buffer ----
__global__ void k_fused0(const float* __restrict__ theta, const float* __restrict__ we) {
    __shared__ float2 vg2_s[Tt * 32];
    __shared__ float  rg_s[Tt * Tt];
    __shared__ float2 we1_2[Dd * 32];
    __shared__ float2 thj1_2[Tt * 32];
    __shared__ float4 p4_s[8][32];
    __shared__ int    pk_s[8][32];
    __shared__ float  h_s[8][Dd];
    int tid = threadIdx.x;              // 256 = 8 warps = 8 nodes
    if (tid < 128) vg2_s[tid] = ((const float2*)g_vg[0])[tid];
    else if (tid < 256) {
        int j = tid - 128;
        thj1_2[j] = make_float2(
            theta[(Tt * 3 * Dd) + (j >> 5) * 3 * Dd + 2 * Dd + (j & 31) * 2],
            theta[(Tt * 3 * Dd) + (j >> 5) * 3 * Dd + 2 * Dd + (j & 31) * 2 + 1]);
    }
    if (tid < Tt * Tt) rg_s[tid] = g_rg[0][tid];
    const float2* w1 = (const float2*)(we + Dd * Dd);
#pragma unroll
    for (int i = 0; i < 8; i++) we1_2[tid + i * 256] = w1[tid + i * 256];
    __syncthreads();
    int w = tid >> 5, lane = tid & 31;
    int n = blockIdx.x * 8 + w;
    int beg = g_off[n], end = g_off[n + 1];
    const float4* sj4p = (const float4*)g_sj0;
    float2 a0 = make_float2(0.f, 0.f), a1 = a0, a2 = a0, a3 = a0;
    float s0 = 0.f, s1 = 0.f, s2 = 0.f, s3 = 0.f;

    int pkbuf = (beg + lane < end) ? g_ect[beg + lane] : 0;
    for (int base = beg; base < end; base += 32) {
        int cnt = min(32, end - base);
        int pk = pkbuf;
        if (base + 32 + lane < end) pkbuf = g_ect[base + 32 + lane];
        float p0 = 0.f, p1 = 0.f, p2 = 0.f, p3 = 0.f;
        if (lane < cnt) {
            float4 sj4 = sj4p[pk & 16383];
            const float* rgc = rg_s + (pk >> 14);
            p0 = __expf(rgc[0]  + sj4.x);
            p1 = __expf(rgc[4]  + sj4.y);
            p2 = __expf(rgc[8]  + sj4.z);
            p3 = __expf(rgc[12] + sj4.w);
        }
        s0 += p0; s1 += p1; s2 += p2; s3 += p3;
        p4_s[w][lane] = make_float4(p0, p1, p2, p3);
        pk_s[w][lane] = pk;
        __syncwarp();
#pragma unroll 4
        for (int i = 0; i < cnt; i++) {
            float4 p = p4_s[w][i];
            int pki = pk_s[w][i];
            int ci = pki & 16383, tyi = pki >> 14;
            float2 h = ((const float2*)(g_hw0 + (size_t)ci * Dd))[lane];
            float2 v = vg2_s[tyi * 32 + lane];
            float vx = v.x * h.x, vy = v.y * h.y;
            a0.x += p.x * vx; a0.y += p.x * vy;
            a1.x += p.y * vx; a1.y += p.y * vy;
            a2.x += p.z * vx; a2.y += p.z * vy;
            a3.x += p.w * vx; a3.y += p.w * vy;
        }
        __syncwarp();
    }
#pragma unroll
    for (int o = 16; o; o >>= 1) {
        s0 += __shfl_xor_sync(0xffffffffu, s0, o);
        s1 += __shfl_xor_sync(0xffffffffu, s1, o);
        s2 += __shfl_xor_sync(0xffffffffu, s2, o);
        s3 += __shfl_xor_sync(0xffffffffu, s3, o);
    }

    float2 acc[Tt] = {a0, a1, a2, a3};
    float ss[Tt] = {s0, s1, s2, s3};
#pragma unroll
    for (int t = 0; t < Tt; t++) {
        float inv = ss[t] > 0.f ? 1.f / ss[t] : 0.f;
        float v0 = fmaxf(acc[t].x * inv, 0.f);
        float v1 = fmaxf(acc[t].y * inv, 0.f);
        h_s[w][2 * lane] = v0; h_s[w][2 * lane + 1] = v1;
        __syncwarp();
        float2 o2 = make_float2(0.f, 0.f);
#pragma unroll
        for (int k = 0; k < Dd; k++) {
            float hv = h_s[w][k];
            float2 wk = we1_2[k * 32 + lane];
            o2.x += hv * wk.x;
            o2.y += hv * wk.y;
        }
        ((float2*)(g_hw1 + (size_t)n * (Tt * Dd) + (size_t)t * Dd))[lane] = o2;
        float2 tj = thj1_2[t * 32 + lane];
        float sj = v0 * tj.x + v1 * tj.y;
#pragma unroll
        for (int o = 16; o; o >>= 1) sj += __shfl_down_sync(0xffffffffu, sj, o);
        if (lane == 0) g_sj1[n * Tt + t] = sj;
        __syncwarp();
    }
}

// ---- fused layer 1: warp per NODE, float2 lanes, contiguous 1KB gather ----
__global__ void k_fused1(float* __restrict__ out) {
    __shared__ float2 vg2_s[Tt * 32];
    __shared__ float  rg_s[Tt * Tt];
    __shared__ float4 p4_s[8][32];
    __shared__ int    pk_s[8][32];
    int tid = threadIdx.x;              // 256 = 8 warps = 8 nodes
    if (tid < 128) vg2_s[tid] = ((const float2*)g_vg[1])[tid];
    if (tid < Tt * Tt) rg_s[tid] = g_rg[1][tid];
    // re-zero deg histogram + scan flags for the next graph replay
    if (blockIdx.x < 64) {
        g_deg[blockIdx.x * 256 + tid] = 0;
        if (blockIdx.x == 0 && tid < 16) g_bflag[tid] = 0;
    }
    __syncthreads();
    int w = tid >> 5, lane = tid & 31;
    int n = blockIdx.x * 8 + w;
    int beg = g_off[n], end = g_off[n + 1];
    const float4* sj4p = (const float4*)g_sj1;
    float2 a0 = make_float2(0.f, 0.f), a1 = a0, a2 = a0, a3 = a0;
    float s0 = 0.f, s1 = 0.f, s2 = 0.f, s3 = 0.f;

    int pkbuf = (beg + lane < end) ? g_ect[beg + lane] : 0;
    for (int base = beg; base < end; base += 32) {
        int cnt = min(32, end - base);
        int pk = pkbuf;
        if (base + 32 + lane < end) pkbuf = g_ect[base + 32 + lane];
        float p0 = 0.f, p1 = 0.f, p2 = 0.f, p3 = 0.f;
        if (lane < cnt) {
            float4 sj4 = sj4p[pk & 16383];
            const float* rgc = rg_s + (pk >> 14);
            p0 = __expf(rgc[0]  + sj4.x);
            p1 = __expf(rgc[4]  + sj4.y);
            p2 = __expf(rgc[8]  + sj4.z);
            p3 = __expf(rgc[12] + sj4.w);
        }
        s0 += p0; s1 += p1; s2 += p2; s3 += p3;
        p4_s[w][lane] = make_float4(p0, p1, p2, p3);
        pk_s[w][lane] = pk;
        __syncwarp();
#pragma unroll 4
        for (int i = 0; i < cnt; i++) {
            float4 p = p4_s[w][i];
            int pki = pk_s[w][i];
            int ci = pki & 16383, tyi = pki >> 14;
            const float2* hp = (const float2*)(g_hw1 + (size_t)ci * (Tt * Dd));
            float2 v = vg2_s[tyi * 32 + lane];
            float2 h0 = hp[lane], h1 = hp[32 + lane], h2 = hp[64 + lane], h3 = hp[96 + lane];
            a0.x += p.x * v.x * h0.x; a0.y += p.x * v.y * h0.y;
            a1.x += p.y * v.x * h1.x; a1.y += p.y * v.y * h1.y;
            a2.x += p.z * v.x * h2.x; a2.y += p.z * v.y * h2.y;
            a3.x += p.w * v.x * h3.x; a3.y += p.w * v.y * h3.y;
        }
        __syncwarp();
    }
#pragma unroll
    for (int o = 16; o; o >>= 1) {
        s0 += __shfl_xor_sync(0xffffffffu, s0, o);
        s1 += __shfl_xor_sync(0xffffffffu, s1, o);
        s2 += __shfl_xor_sync(0xffffffffu, s2, o);
        s3 += __shfl_xor_sync(0xffffffffu, s3, o);
    }
    float2 acc[Tt] = {a0, a1, a2, a3};
    float ss[Tt] = {s0, s1, s2, s3};
#pragma unroll
    for (int t = 0; t < Tt; t++) {
        float inv = ss[t] > 0.f ? 1.f / ss[t] : 0.f;
        float2 o2 = make_float2(acc[t].x * inv, acc[t].y * inv);
        ((float2*)(out + (size_t)t * (Nn * Dd) + (size_t)n * Dd))[lane] = o2;
    }
}

extern "C" void kernel_launch(void* const* d_in, const int* in_sizes, int n_in,
                              void* d_out, int out_size) {
    const float* x     = (const float*)d_in[0];
    const float* ef0   = (const float*)d_in[1];
    const float* theta = (const float*)d_in[2];
    const float* wr    = (const float*)d_in[3];
    const float* we    = (const float*)d_in[4];
    const void*  eidx  = d_in[5];
    const void*  etyp  = d_in[6];
    float* out = (float*)d_out;

    k_hist<<<Ee / 1024, 256>>>(eidx, etyp);
    k_mid<<<16 + 1 + Nn / 32, 256>>>(x, ef0, we, theta, wr);
    k_scatter<<<Ee / 2048, 256>>>();
    k_fused0<<<Nn / 8, 256>>>(theta, we);
    k_fused1<<<Nn / 8, 256>>>(out);
}

// round 14
// speedup vs baseline: 1.1397x; 1.1397x over previous
#include <cuda_runtime.h>
#include <math.h>

#define Nn 16384
#define Ee 262144
#define Tt 4
#define Dd 64
#define TND (Tt*Nn*Dd)

// ---- scratch (zero-initialized at load; fused1 re-zeros deg/flags each run) ----
__device__ int   g_rr[Ee];            // packed (row | rank<<14)
__device__ int   g_cet[Ee];           // raw packed (col | ty<<14)
__device__ int   g_ect[Ee];           // CSR-sorted packed
__device__ int   g_deg[Nn], g_off[Nn + 1];
__device__ int   g_bval[16], g_bflag[16];
__device__ float g_hw0[Nn * Dd];      // x @ we0 (single plane)
__device__ float g_h1[TND];           // layer-1 input h, INTERLEAVED [n][t][d]
__device__ float g_hw1[TND];          // h1 @ we1, INTERLEAVED [n][t][d]
__device__ float g_sj0[Nn * Tt];      // interleaved [n][t]
__device__ float g_sj1[Nn * Tt];
__device__ float g_rg[2][Tt * Tt];
__device__ float g_vg[2][Tt * Dd];

// ---- hist: per-thread dtype detect + degree count ----
__global__ void k_hist(const void* __restrict__ eidx, const void* __restrict__ etyp) {
    int i = blockIdx.x * blockDim.x + threadIdx.x;   // Ee/4 threads
    const long long* p = (const long long*)eidx;
    long long d0 = p[4 * i], d1 = p[4 * i + 1], d2 = p[4 * i + 2], d3 = p[4 * i + 3];
    bool is64 = ((unsigned long long)(d0 | d1 | d2 | d3)) < (unsigned long long)Nn;
    int4 rv, cv, tv;
    if (is64) {
        const long long* q = (const long long*)etyp;
        rv = make_int4((int)d0, (int)d1, (int)d2, (int)d3);
        int e = i * 4;
        cv = make_int4((int)p[Ee + e], (int)p[Ee + e + 1], (int)p[Ee + e + 2], (int)p[Ee + e + 3]);
        tv = make_int4((int)q[e], (int)q[e + 1], (int)q[e + 2], (int)q[e + 3]);
    } else {
        rv = ((const int4*)eidx)[i];
        cv = ((const int4*)eidx)[Ee / 4 + i];
        tv = ((const int4*)etyp)[i];
    }
    int4 rr, ce;
    rr.x = rv.x | (atomicAdd(&g_deg[rv.x], 1) << 14);
    rr.y = rv.y | (atomicAdd(&g_deg[rv.y], 1) << 14);
    rr.z = rv.z | (atomicAdd(&g_deg[rv.z], 1) << 14);
    rr.w = rv.w | (atomicAdd(&g_deg[rv.w], 1) << 14);
    ce.x = cv.x | (tv.x << 14);
    ce.y = cv.y | (tv.y << 14);
    ce.z = cv.z | (tv.z << 14);
    ce.w = cv.w | (tv.w << 14);
    ((int4*)g_rr)[i]  = rr;
    ((int4*)g_cet)[i] = ce;
}

// ---- rgef for BOTH layers ----
__device__ void rgef_body(const float* __restrict__ ef0, const float* __restrict__ theta,
                          const float* __restrict__ wr) {
    __shared__ float efa[Tt * Dd], efb[Tt * Dd];
    int tid = threadIdx.x;              // 256
    int t = tid >> 6, d = tid & 63;
    efa[tid] = ef0[tid];
    __syncthreads();
    if (tid < Tt * Tt) {
        int t1 = tid >> 2, t2 = tid & 3;
        const float* tg = theta + t1 * 3 * Dd;
        float s = 0.f;
#pragma unroll
        for (int k = 0; k < Dd; k++) s += tg[k] * efa[t2 * Dd + k];
        g_rg[0][tid] = s;
    }
    {
        float s = 0.f;
#pragma unroll
        for (int k = 0; k < Dd; k++) s += efa[t * Dd + k] * wr[k * Dd + d];
        g_vg[0][tid] = 1.f / (1.f + __expf(-s));
        efb[tid] = fmaxf(s, 0.f);
    }
    __syncthreads();
    if (tid < Tt * Tt) {
        int t1 = tid >> 2, t2 = tid & 3;
        const float* tg = theta + (Tt * 3 * Dd) + t1 * 3 * Dd;
        float s = 0.f;
#pragma unroll
        for (int k = 0; k < Dd; k++) s += tg[k] * efb[t2 * Dd + k];
        g_rg[1][tid] = s;
    }
    {
        const float* w1 = wr + Dd * Dd;
        float s = 0.f;
#pragma unroll
        for (int k = 0; k < Dd; k++) s += efb[t * Dd + k] * w1[k * Dd + d];
        g_vg[1][tid] = 1.f / (1.f + __expf(-s));
    }
}

// ---- scan body: 256 threads x int4, decoupled lookback (blocks 0..15) ----
__device__ void scan_body(int b) {
    __shared__ int sh[256];
    __shared__ int base_s;
    int tid = threadIdx.x;
    int i4 = b * 256 + tid;
    int4 v = ((const int4*)g_deg)[i4];
    int lsum = v.x + v.y + v.z + v.w;
    sh[tid] = lsum;
    __syncthreads();
    for (int off = 1; off < 256; off <<= 1) {
        int u = (tid >= off) ? sh[tid - off] : 0;
        __syncthreads();
        sh[tid] += u;
        __syncthreads();
    }
    if (tid == 255) {
        g_bval[b] = sh[255];
        __threadfence();
        atomicExch(&g_bflag[b], 1);
    }
    if (tid == 0) {
        int acc = 0;
        for (int j = 0; j < b; j++) {
            while (atomicAdd(&g_bflag[j], 0) == 0) { }
            acc += g_bval[j];
        }
        base_s = acc;
    }
    __syncthreads();
    int o = base_s + sh[tid] - lsum;
    int4 off4;
    off4.x = o;
    off4.y = o + v.x;
    off4.z = o + v.x + v.y;
    off4.w = o + v.x + v.y + v.z;
    ((int4*)g_off)[i4] = off4;
    if (b == 15 && tid == 255) g_off[Nn] = Ee;
}

// ---- gemm0 body: hw0 = x @ we0 + sj0 (blocks 17..) ----
__device__ void gemm0_body(int blk, const float* __restrict__ x,
                           const float* __restrict__ we, const float* __restrict__ theta) {
    __shared__ float we_s[Dd * Dd];
    __shared__ float h_s[32 * Dd];
    __shared__ float thj_s[Tt * Dd];
    int tid = threadIdx.x;              // 256
    int n0 = blk * 32;
#pragma unroll
    for (int i = 0; i < 16; i++) we_s[tid + i * 256] = we[tid + i * 256];
    const float* hb = x + (size_t)n0 * Dd;
#pragma unroll
    for (int i = 0; i < 8; i++) h_s[tid + i * 256] = hb[tid + i * 256];
    {
        int t = tid >> 6, d = tid & 63;
        thj_s[t * Dd + d] = theta[t * 3 * Dd + 2 * Dd + d];
    }
    __syncthreads();
    int d = tid & 63, ng = tid >> 6;
    float acc[8] = {0.f, 0.f, 0.f, 0.f, 0.f, 0.f, 0.f, 0.f};
#pragma unroll
    for (int k = 0; k < Dd; k++) {
        float wv = we_s[k * Dd + d];
#pragma unroll
        for (int j = 0; j < 8; j++) acc[j] += h_s[(ng * 8 + j) * Dd + k] * wv;
    }
    float* ob = g_hw0 + (size_t)n0 * Dd;
#pragma unroll
    for (int j = 0; j < 8; j++) ob[(ng * 8 + j) * Dd + d] = acc[j];

    int wid = tid >> 5, lane = tid & 31;
#pragma unroll
    for (int j = 0; j < 4; j++) {
        int nl = wid * 4 + j;
        float a = h_s[nl * Dd + lane], b = h_s[nl * Dd + lane + 32];
#pragma unroll
        for (int t = 0; t < Tt; t++) {
            float sj = a * thj_s[t * Dd + lane] + b * thj_s[t * Dd + lane + 32];
#pragma unroll
            for (int o = 16; o; o >>= 1) sj += __shfl_down_sync(0xffffffffu, sj, o);
            if (lane == 0) g_sj0[(n0 + nl) * Tt + t] = sj;
        }
    }
}

// ---- mid: scan (0..15) | rgef (16) | gemm0 (17..) ----
__global__ void k_mid(const float* __restrict__ x, const float* __restrict__ ef0,
                      const float* __restrict__ we, const float* __restrict__ theta,
                      const float* __restrict__ wr) {
    int b = blockIdx.x;
    if (b < 16) { scan_body(b); return; }
    if (b == 16) { rgef_body(ef0, theta, wr); return; }
    gemm0_body(b - 17, x, we, theta);
}

// ---- scatter: atomic-free, 8 edges/thread ----
__global__ void k_scatter() {
    int i = blockIdx.x * blockDim.x + threadIdx.x;
    int4 r0 = ((const int4*)g_rr)[2 * i];
    int4 r1 = ((const int4*)g_rr)[2 * i + 1];
    int4 c0 = ((const int4*)g_cet)[2 * i];
    int4 c1 = ((const int4*)g_cet)[2 * i + 1];
    int p0 = g_off[r0.x & 16383] + (((unsigned)r0.x) >> 14);
    int p1 = g_off[r0.y & 16383] + (((unsigned)r0.y) >> 14);
    int p2 = g_off[r0.z & 16383] + (((unsigned)r0.z) >> 14);
    int p3 = g_off[r0.w & 16383] + (((unsigned)r0.w) >> 14);
    int p4 = g_off[r1.x & 16383] + (((unsigned)r1.x) >> 14);
    int p5 = g_off[r1.y & 16383] + (((unsigned)r1.y) >> 14);
    int p6 = g_off[r1.z & 16383] + (((unsigned)r1.z) >> 14);
    int p7 = g_off[r1.w & 16383] + (((unsigned)r1.w) >> 14);
    g_ect[p0] = c0.x; g_ect[p1] = c0.y; g_ect[p2] = c0.z; g_ect[p3] = c0.w;
    g_ect[p4] = c1.x; g_ect[p5] = c1.y; g_ect[p6] = c1.z; g_ect[p7] = c1.w;
}

// ---- fused layer 0: warp per NODE; LIGHT epilogue (h1 + sj1 only) ----
__global__ void k_fused0(const float* __restrict__ theta) {
    __shared__ float2 vg2_s[Tt * 32];
    __shared__ float  rg_s[Tt * Tt];
    __shared__ float2 thj1_2[Tt * 32];
    __shared__ float4 p4_s[8][32];
    __shared__ int    pk_s[8][32];
    int tid = threadIdx.x;              // 256 = 8 warps = 8 nodes
    if (tid < 128) vg2_s[tid] = ((const float2*)g_vg[0])[tid];
    else {
        int j = tid - 128;
        thj1_2[j] = make_float2(
            theta[(Tt * 3 * Dd) + (j >> 5) * 3 * Dd + 2 * Dd + (j & 31) * 2],
            theta[(Tt * 3 * Dd) + (j >> 5) * 3 * Dd + 2 * Dd + (j & 31) * 2 + 1]);
    }
    if (tid < Tt * Tt) rg_s[tid] = g_rg[0][tid];
    __syncthreads();
    int w = tid >> 5, lane = tid & 31;
    int n = blockIdx.x * 8 + w;
    int beg = g_off[n], end = g_off[n + 1];
    const float4* sj4p = (const float4*)g_sj0;
    float2 a0 = make_float2(0.f, 0.f), a1 = a0, a2 = a0, a3 = a0;
    float s0 = 0.f, s1 = 0.f, s2 = 0.f, s3 = 0.f;

    int pkbuf = (beg + lane < end) ? g_ect[beg + lane] : 0;
    for (int base = beg; base < end; base += 32) {
        int cnt = min(32, end - base);
        int pk = pkbuf;
        if (base + 32 + lane < end) pkbuf = g_ect[base + 32 + lane];
        float p0 = 0.f, p1 = 0.f, p2 = 0.f, p3 = 0.f;
        if (lane < cnt) {
            float4 sj4 = sj4p[pk & 16383];
            const float* rgc = rg_s + (pk >> 14);
            p0 = __expf(rgc[0]  + sj4.x);
            p1 = __expf(rgc[4]  + sj4.y);
            p2 = __expf(rgc[8]  + sj4.z);
            p3 = __expf(rgc[12] + sj4.w);
        }
        s0 += p0; s1 += p1; s2 += p2; s3 += p3;
        p4_s[w][lane] = make_float4(p0, p1, p2, p3);
        pk_s[w][lane] = pk;
        __syncwarp();
#pragma unroll 4
        for (int i = 0; i < cnt; i++) {
            float4 p = p4_s[w][i];
            int pki = pk_s[w][i];
            int ci = pki & 16383, tyi = pki >> 14;
            float2 h = ((const float2*)(g_hw0 + (size_t)ci * Dd))[lane];
            float2 v = vg2_s[tyi * 32 + lane];
            float vx = v.x * h.x, vy = v.y * h.y;
            a0.x += p.x * vx; a0.y += p.x * vy;
            a1.x += p.y * vx; a1.y += p.y * vy;
            a2.x += p.z * vx; a2.y += p.z * vy;
            a3.x += p.w * vx; a3.y += p.w * vy;
        }
        __syncwarp();
    }
#pragma unroll
    for (int o = 16; o; o >>= 1) {
        s0 += __shfl_xor_sync(0xffffffffu, s0, o);
        s1 += __shfl_xor_sync(0xffffffffu, s1, o);
        s2 += __shfl_xor_sync(0xffffffffu, s2, o);
        s3 += __shfl_xor_sync(0xffffffffu, s3, o);
    }

    float2 acc[Tt] = {a0, a1, a2, a3};
    float ss[Tt] = {s0, s1, s2, s3};
#pragma unroll
    for (int t = 0; t < Tt; t++) {
        float inv = ss[t] > 0.f ? 1.f / ss[t] : 0.f;
        float v0 = fmaxf(acc[t].x * inv, 0.f);
        float v1 = fmaxf(acc[t].y * inv, 0.f);
        ((float2*)(g_h1 + ((size_t)n * Tt + t) * Dd))[lane] = make_float2(v0, v1);
        float2 tj = thj1_2[t * 32 + lane];
        float sj = v0 * tj.x + v1 * tj.y;
#pragma unroll
        for (int o = 16; o; o >>= 1) sj += __shfl_down_sync(0xffffffffu, sj, o);
        if (lane == 0) g_sj1[n * Tt + t] = sj;
    }
}

// ---- gemm1: hw1[n][t][:] = h1[n][t][:] @ we1, block = (32 nodes, one t) ----
__global__ void k_gemm1(const float* __restrict__ we) {
    __shared__ float we_s[Dd * Dd];
    __shared__ float h_s[32 * Dd];
    int tid = threadIdx.x;              // 256
    int t = blockIdx.y;
    int n0 = blockIdx.x * 32;
    const float* w1 = we + Dd * Dd;
#pragma unroll
    for (int i = 0; i < 16; i++) we_s[tid + i * 256] = w1[tid + i * 256];
#pragma unroll
    for (int i = 0; i < 8; i++) {
        int idx = tid + i * 256;
        int row = idx >> 6, d = idx & 63;
        h_s[row * Dd + d] = g_h1[((size_t)(n0 + row) * Tt + t) * Dd + d];
    }
    __syncthreads();
    int d = tid & 63, ng = tid >> 6;
    float acc[8] = {0.f, 0.f, 0.f, 0.f, 0.f, 0.f, 0.f, 0.f};
#pragma unroll
    for (int k = 0; k < Dd; k++) {
        float wv = we_s[k * Dd + d];
#pragma unroll
        for (int j = 0; j < 8; j++) acc[j] += h_s[(ng * 8 + j) * Dd + k] * wv;
    }
#pragma unroll
    for (int j = 0; j < 8; j++)
        g_hw1[((size_t)(n0 + ng * 8 + j) * Tt + t) * Dd + d] = acc[j];
}

// ---- fused layer 1: warp per NODE, contiguous 1KB hw1 gather ----
__global__ void k_fused1(float* __restrict__ out) {
    __shared__ float2 vg2_s[Tt * 32];
    __shared__ float  rg_s[Tt * Tt];
    __shared__ float4 p4_s[8][32];
    __shared__ int    pk_s[8][32];
    int tid = threadIdx.x;              // 256 = 8 warps = 8 nodes
    if (tid < 128) vg2_s[tid] = ((const float2*)g_vg[1])[tid];
    if (tid < Tt * Tt) rg_s[tid] = g_rg[1][tid];
    // re-zero deg histogram + scan flags for the next graph replay
    if (blockIdx.x < 64) {
        g_deg[blockIdx.x * 256 + tid] = 0;
        if (blockIdx.x == 0 && tid < 16) g_bflag[tid] = 0;
    }
    __syncthreads();
    int w = tid >> 5, lane = tid & 31;
    int n = blockIdx.x * 8 + w;
    int beg = g_off[n], end = g_off[n + 1];
    const float4* sj4p = (const float4*)g_sj1;
    float2 a0 = make_float2(0.f, 0.f), a1 = a0, a2 = a0, a3 = a0;
    float s0 = 0.f, s1 = 0.f, s2 = 0.f, s3 = 0.f;

    int pkbuf = (beg + lane < end) ? g_ect[beg + lane] : 0;
    for (int base = beg; base < end; base += 32) {
        int cnt = min(32, end - base);
        int pk = pkbuf;
        if (base + 32 + lane < end) pkbuf = g_ect[base + 32 + lane];
        float p0 = 0.f, p1 = 0.f, p2 = 0.f, p3 = 0.f;
        if (lane < cnt) {
            float4 sj4 = sj4p[pk & 16383];
            const float* rgc = rg_s + (pk >> 14);
            p0 = __expf(rgc[0]  + sj4.x);
            p1 = __expf(rgc[4]  + sj4.y);
            p2 = __expf(rgc[8]  + sj4.z);
            p3 = __expf(rgc[12] + sj4.w);
        }
        s0 += p0; s1 += p1; s2 += p2; s3 += p3;
        p4_s[w][lane] = make_float4(p0, p1, p2, p3);
        pk_s[w][lane] = pk;
        __syncwarp();
#pragma unroll 4
        for (int i = 0; i < cnt; i++) {
            float4 p = p4_s[w][i];
            int pki = pk_s[w][i];
            int ci = pki & 16383, tyi = pki >> 14;
            const float2* hp = (const float2*)(g_hw1 + (size_t)ci * (Tt * Dd));
            float2 v = vg2_s[tyi * 32 + lane];
            float2 h0 = hp[lane], h1 = hp[32 + lane], h2 = hp[64 + lane], h3 = hp[96 + lane];
            a0.x += p.x * v.x * h0.x; a0.y += p.x * v.y * h0.y;
            a1.x += p.y * v.x * h1.x; a1.y += p.y * v.y * h1.y;
            a2.x += p.z * v.x * h2.x; a2.y += p.z * v.y * h2.y;
            a3.x += p.w * v.x * h3.x; a3.y += p.w * v.y * h3.y;
        }
        __syncwarp();
    }
#pragma unroll
    for (int o = 16; o; o >>= 1) {
        s0 += __shfl_xor_sync(0xffffffffu, s0, o);
        s1 += __shfl_xor_sync(0xffffffffu, s1, o);
        s2 += __shfl_xor_sync(0xffffffffu, s2, o);
        s3 += __shfl_xor_sync(0xffffffffu, s3, o);
    }
    float2 acc[Tt] = {a0, a1, a2, a3};
    float ss[Tt] = {s0, s1, s2, s3};
#pragma unroll
    for (int t = 0; t < Tt; t++) {
        float inv = ss[t] > 0.f ? 1.f / ss[t] : 0.f;
        float2 o2 = make_float2(acc[t].x * inv, acc[t].y * inv);
        ((float2*)(out + (size_t)t * (Nn * Dd) + (size_t)n * Dd))[lane] = o2;
    }
}

extern "C" void kernel_launch(void* const* d_in, const int* in_sizes, int n_in,
                              void* d_out, int out_size) {
    const float* x     = (const float*)d_in[0];
    const float* ef0   = (const float*)d_in[1];
    const float* theta = (const float*)d_in[2];
    const float* wr    = (const float*)d_in[3];
    const float* we    = (const float*)d_in[4];
    const void*  eidx  = d_in[5];
    const void*  etyp  = d_in[6];
    float* out = (float*)d_out;

    k_hist<<<Ee / 1024, 256>>>(eidx, etyp);
    k_mid<<<16 + 1 + Nn / 32, 256>>>(x, ef0, we, theta, wr);
    k_scatter<<<Ee / 2048, 256>>>();
    k_fused0<<<Nn / 8, 256>>>(theta);
    k_gemm1<<<dim3(Nn / 32, Tt), 256>>>(we);
    k_fused1<<<Nn / 8, 256>>>(out);
}

// round 15
// speedup vs baseline: 1.1610x; 1.0187x over previous
#include <cuda_runtime.h>
#include <math.h>

#define Nn 16384
#define Ee 262144
#define Tt 4
#define Dd 64
#define TND (Tt*Nn*Dd)

// ---- scratch (zero-initialized at load; fused1 re-zeros deg/flags each run) ----
__device__ int   g_rr[Ee];            // packed (row | rank<<14)
__device__ int   g_cet[Ee];           // raw packed (col | ty<<14)
__device__ int   g_ect[Ee];           // CSR-sorted packed
__device__ int   g_deg[Nn], g_off[Nn + 1];
__device__ int   g_bval[16], g_bflag[16];
__device__ float g_hw0[Nn * Dd];      // x @ we0 (single plane)
__device__ float g_hw1[TND];          // h1 @ we1, INTERLEAVED [n][t][d]
__device__ float g_sj0[Nn * Tt];      // interleaved [n][t]
__device__ float g_sj1[Nn * Tt];
__device__ float g_rg[2][Tt * Tt];
__device__ float g_vg[2][Tt * Dd];

// ---- hist: per-thread dtype detect + degree count ----
__global__ void k_hist(const void* __restrict__ eidx, const void* __restrict__ etyp) {
    int i = blockIdx.x * blockDim.x + threadIdx.x;   // Ee/4 threads
    const long long* p = (const long long*)eidx;
    long long d0 = p[4 * i], d1 = p[4 * i + 1], d2 = p[4 * i + 2], d3 = p[4 * i + 3];
    bool is64 = ((unsigned long long)(d0 | d1 | d2 | d3)) < (unsigned long long)Nn;
    int4 rv, cv, tv;
    if (is64) {
        const long long* q = (const long long*)etyp;
        rv = make_int4((int)d0, (int)d1, (int)d2, (int)d3);
        int e = i * 4;
        cv = make_int4((int)p[Ee + e], (int)p[Ee + e + 1], (int)p[Ee + e + 2], (int)p[Ee + e + 3]);
        tv = make_int4((int)q[e], (int)q[e + 1], (int)q[e + 2], (int)q[e + 3]);
    } else {
        rv = ((const int4*)eidx)[i];
        cv = ((const int4*)eidx)[Ee / 4 + i];
        tv = ((const int4*)etyp)[i];
    }
    int4 rr, ce;
    rr.x = rv.x | (atomicAdd(&g_deg[rv.x], 1) << 14);
    rr.y = rv.y | (atomicAdd(&g_deg[rv.y], 1) << 14);
    rr.z = rv.z | (atomicAdd(&g_deg[rv.z], 1) << 14);
    rr.w = rv.w | (atomicAdd(&g_deg[rv.w], 1) << 14);
    ce.x = cv.x | (tv.x << 14);
    ce.y = cv.y | (tv.y << 14);
    ce.z = cv.z | (tv.z << 14);
    ce.w = cv.w | (tv.w << 14);
    ((int4*)g_rr)[i]  = rr;
    ((int4*)g_cet)[i] = ce;
}

// ---- rgef for BOTH layers ----
__device__ void rgef_body(const float* __restrict__ ef0, const float* __restrict__ theta,
                          const float* __restrict__ wr) {
    __shared__ float efa[Tt * Dd], efb[Tt * Dd];
    int tid = threadIdx.x;              // 256
    int t = tid >> 6, d = tid & 63;
    efa[tid] = ef0[tid];
    __syncthreads();
    if (tid < Tt * Tt) {
        int t1 = tid >> 2, t2 = tid & 3;
        const float* tg = theta + t1 * 3 * Dd;
        float s = 0.f;
#pragma unroll
        for (int k = 0; k < Dd; k++) s += tg[k] * efa[t2 * Dd + k];
        g_rg[0][tid] = s;
    }
    {
        float s = 0.f;
#pragma unroll
        for (int k = 0; k < Dd; k++) s += efa[t * Dd + k] * wr[k * Dd + d];
        g_vg[0][tid] = 1.f / (1.f + __expf(-s));
        efb[tid] = fmaxf(s, 0.f);
    }
    __syncthreads();
    if (tid < Tt * Tt) {
        int t1 = tid >> 2, t2 = tid & 3;
        const float* tg = theta + (Tt * 3 * Dd) + t1 * 3 * Dd;
        float s = 0.f;
#pragma unroll
        for (int k = 0; k < Dd; k++) s += tg[k] * efb[t2 * Dd + k];
        g_rg[1][tid] = s;
    }
    {
        const float* w1 = wr + Dd * Dd;
        float s = 0.f;
#pragma unroll
        for (int k = 0; k < Dd; k++) s += efb[t * Dd + k] * w1[k * Dd + d];
        g_vg[1][tid] = 1.f / (1.f + __expf(-s));
    }
}

// ---- scan body: 256 threads x int4, decoupled lookback (blocks 0..15) ----
__device__ void scan_body(int b) {
    __shared__ int sh[256];
    __shared__ int base_s;
    int tid = threadIdx.x;
    int i4 = b * 256 + tid;
    int4 v = ((const int4*)g_deg)[i4];
    int lsum = v.x + v.y + v.z + v.w;
    sh[tid] = lsum;
    __syncthreads();
    for (int off = 1; off < 256; off <<= 1) {
        int u = (tid >= off) ? sh[tid - off] : 0;
        __syncthreads();
        sh[tid] += u;
        __syncthreads();
    }
    if (tid == 255) {
        g_bval[b] = sh[255];
        __threadfence();
        atomicExch(&g_bflag[b], 1);
    }
    if (tid == 0) {
        int acc = 0;
        for (int j = 0; j < b; j++) {
            while (atomicAdd(&g_bflag[j], 0) == 0) { }
            acc += g_bval[j];
        }
        base_s = acc;
    }
    __syncthreads();
    int o = base_s + sh[tid] - lsum;
    int4 off4;
    off4.x = o;
    off4.y = o + v.x;
    off4.z = o + v.x + v.y;
    off4.w = o + v.x + v.y + v.z;
    ((int4*)g_off)[i4] = off4;
    if (b == 15 && tid == 255) g_off[Nn] = Ee;
}

// ---- gemm0 body: hw0 = x @ we0 + sj0 (blocks 17..) ----
__device__ void gemm0_body(int blk, const float* __restrict__ x,
                           const float* __restrict__ we, const float* __restrict__ theta) {
    __shared__ float we_s[Dd * Dd];
    __shared__ float h_s[32 * Dd];
    __shared__ float thj_s[Tt * Dd];
    int tid = threadIdx.x;              // 256
    int n0 = blk * 32;
#pragma unroll
    for (int i = 0; i < 16; i++) we_s[tid + i * 256] = we[tid + i * 256];
    const float* hb = x + (size_t)n0 * Dd;
#pragma unroll
    for (int i = 0; i < 8; i++) h_s[tid + i * 256] = hb[tid + i * 256];
    {
        int t = tid >> 6, d = tid & 63;
        thj_s[t * Dd + d] = theta[t * 3 * Dd + 2 * Dd + d];
    }
    __syncthreads();
    int d = tid & 63, ng = tid >> 6;
    float acc[8] = {0.f, 0.f, 0.f, 0.f, 0.f, 0.f, 0.f, 0.f};
#pragma unroll
    for (int k = 0; k < Dd; k++) {
        float wv = we_s[k * Dd + d];
#pragma unroll
        for (int j = 0; j < 8; j++) acc[j] += h_s[(ng * 8 + j) * Dd + k] * wv;
    }
    float* ob = g_hw0 + (size_t)n0 * Dd;
#pragma unroll
    for (int j = 0; j < 8; j++) ob[(ng * 8 + j) * Dd + d] = acc[j];

    int wid = tid >> 5, lane = tid & 31;
#pragma unroll
    for (int j = 0; j < 4; j++) {
        int nl = wid * 4 + j;
        float a = h_s[nl * Dd + lane], b = h_s[nl * Dd + lane + 32];
#pragma unroll
        for (int t = 0; t < Tt; t++) {
            float sj = a * thj_s[t * Dd + lane] + b * thj_s[t * Dd + lane + 32];
#pragma unroll
            for (int o = 16; o; o >>= 1) sj += __shfl_down_sync(0xffffffffu, sj, o);
            if (lane == 0) g_sj0[(n0 + nl) * Tt + t] = sj;
        }
    }
}

// ---- mid: scan (0..15) | rgef (16) | gemm0 (17..) ----
__global__ void k_mid(const float* __restrict__ x, const float* __restrict__ ef0,
                      const float* __restrict__ we, const float* __restrict__ theta,
                      const float* __restrict__ wr) {
    int b = blockIdx.x;
    if (b < 16) { scan_body(b); return; }
    if (b == 16) { rgef_body(ef0, theta, wr); return; }
    gemm0_body(b - 17, x, we, theta);
}

// ---- scatter: atomic-free, 8 edges/thread ----
__global__ void k_scatter() {
    int i = blockIdx.x * blockDim.x + threadIdx.x;
    int4 r0 = ((const int4*)g_rr)[2 * i];
    int4 r1 = ((const int4*)g_rr)[2 * i + 1];
    int4 c0 = ((const int4*)g_cet)[2 * i];
    int4 c1 = ((const int4*)g_cet)[2 * i + 1];
    int p0 = g_off[r0.x & 16383] + (((unsigned)r0.x) >> 14);
    int p1 = g_off[r0.y & 16383] + (((unsigned)r0.y) >> 14);
    int p2 = g_off[r0.z & 16383] + (((unsigned)r0.z) >> 14);
    int p3 = g_off[r0.w & 16383] + (((unsigned)r0.w) >> 14);
    int p4 = g_off[r1.x & 16383] + (((unsigned)r1.x) >> 14);
    int p5 = g_off[r1.y & 16383] + (((unsigned)r1.y) >> 14);
    int p6 = g_off[r1.z & 16383] + (((unsigned)r1.z) >> 14);
    int p7 = g_off[r1.w & 16383] + (((unsigned)r1.w) >> 14);
    g_ect[p0] = c0.x; g_ect[p1] = c0.y; g_ect[p2] = c0.z; g_ect[p3] = c0.w;
    g_ect[p4] = c1.x; g_ect[p5] = c1.y; g_ect[p6] = c1.z; g_ect[p7] = c1.w;
}

// ---- fused layer 0: warp per NODE; epilogue = h1->shared, sj1, then
//      BLOCK-WIDE hw1 GEMM (32 rows = 8 nodes x 4 t; we1 loaded once/block) ----
__global__ void k_fused0(const float* __restrict__ theta, const float* __restrict__ we) {
    __shared__ float2 vg2_s[Tt * 32];
    __shared__ float  rg_s[Tt * Tt];
    __shared__ float2 thj1_2[Tt * 32];
    __shared__ float4 p4_s[8][32];
    __shared__ int    pk_s[8][32];
    __shared__ float  we1_s[Dd * Dd];     // 16KB
    __shared__ float  h_all[32 * Dd];     // 8KB: row = nodeLocal*4 + t
    int tid = threadIdx.x;              // 256 = 8 warps = 8 nodes
    if (tid < 128) vg2_s[tid] = ((const float2*)g_vg[0])[tid];
    else {
        int j = tid - 128;
        thj1_2[j] = make_float2(
            theta[(Tt * 3 * Dd) + (j >> 5) * 3 * Dd + 2 * Dd + (j & 31) * 2],
            theta[(Tt * 3 * Dd) + (j >> 5) * 3 * Dd + 2 * Dd + (j & 31) * 2 + 1]);
    }
    if (tid < Tt * Tt) rg_s[tid] = g_rg[0][tid];
    const float* w1 = we + Dd * Dd;
#pragma unroll
    for (int i = 0; i < 16; i++) we1_s[tid + i * 256] = w1[tid + i * 256];
    __syncthreads();
    int w = tid >> 5, lane = tid & 31;
    int n = blockIdx.x * 8 + w;
    int beg = g_off[n], end = g_off[n + 1];
    const float4* sj4p = (const float4*)g_sj0;
    float2 a0 = make_float2(0.f, 0.f), a1 = a0, a2 = a0, a3 = a0;
    float s0 = 0.f, s1 = 0.f, s2 = 0.f, s3 = 0.f;

    int pkbuf = (beg + lane < end) ? g_ect[beg + lane] : 0;
    for (int base = beg; base < end; base += 32) {
        int cnt = min(32, end - base);
        int pk = pkbuf;
        if (base + 32 + lane < end) pkbuf = g_ect[base + 32 + lane];
        float p0 = 0.f, p1 = 0.f, p2 = 0.f, p3 = 0.f;
        if (lane < cnt) {
            float4 sj4 = sj4p[pk & 16383];
            const float* rgc = rg_s + (pk >> 14);
            p0 = __expf(rgc[0]  + sj4.x);
            p1 = __expf(rgc[4]  + sj4.y);
            p2 = __expf(rgc[8]  + sj4.z);
            p3 = __expf(rgc[12] + sj4.w);
        }
        s0 += p0; s1 += p1; s2 += p2; s3 += p3;
        p4_s[w][lane] = make_float4(p0, p1, p2, p3);
        pk_s[w][lane] = pk;
        __syncwarp();
#pragma unroll 4
        for (int i = 0; i < cnt; i++) {
            float4 p = p4_s[w][i];
            int pki = pk_s[w][i];
            int ci = pki & 16383, tyi = pki >> 14;
            float2 h = ((const float2*)(g_hw0 + (size_t)ci * Dd))[lane];
            float2 v = vg2_s[tyi * 32 + lane];
            float vx = v.x * h.x, vy = v.y * h.y;
            a0.x += p.x * vx; a0.y += p.x * vy;
            a1.x += p.y * vx; a1.y += p.y * vy;
            a2.x += p.z * vx; a2.y += p.z * vy;
            a3.x += p.w * vx; a3.y += p.w * vy;
        }
        __syncwarp();
    }
#pragma unroll
    for (int o = 16; o; o >>= 1) {
        s0 += __shfl_xor_sync(0xffffffffu, s0, o);
        s1 += __shfl_xor_sync(0xffffffffu, s1, o);
        s2 += __shfl_xor_sync(0xffffffffu, s2, o);
        s3 += __shfl_xor_sync(0xffffffffu, s3, o);
    }

    float2 acc[Tt] = {a0, a1, a2, a3};
    float ss[Tt] = {s0, s1, s2, s3};
#pragma unroll
    for (int t = 0; t < Tt; t++) {
        float inv = ss[t] > 0.f ? 1.f / ss[t] : 0.f;
        float v0 = fmaxf(acc[t].x * inv, 0.f);
        float v1 = fmaxf(acc[t].y * inv, 0.f);
        int row = w * 4 + t;
        h_all[row * Dd + 2 * lane]     = v0;
        h_all[row * Dd + 2 * lane + 1] = v1;
        float2 tj = thj1_2[t * 32 + lane];
        float sj = v0 * tj.x + v1 * tj.y;
#pragma unroll
        for (int o = 16; o; o >>= 1) sj += __shfl_down_sync(0xffffffffu, sj, o);
        if (lane == 0) g_sj1[n * Tt + t] = sj;
    }
    __syncthreads();

    // block-wide GEMM: hw1[rows 0..31] = h_all @ we1
    int d = tid & 63, ng = tid >> 6;
    float gacc[8] = {0.f, 0.f, 0.f, 0.f, 0.f, 0.f, 0.f, 0.f};
#pragma unroll
    for (int k = 0; k < Dd; k++) {
        float wv = we1_s[k * Dd + d];
#pragma unroll
        for (int j = 0; j < 8; j++) gacc[j] += h_all[(ng * 8 + j) * Dd + k] * wv;
    }
    size_t ob = ((size_t)blockIdx.x * 8) * (Tt * Dd);   // rows map directly: [n][t][d]
#pragma unroll
    for (int j = 0; j < 8; j++)
        g_hw1[ob + (size_t)(ng * 8 + j) * Dd + d] = gacc[j];
}

// ---- fused layer 1: warp per NODE, contiguous 1KB hw1 gather ----
__global__ void k_fused1(float* __restrict__ out) {
    __shared__ float2 vg2_s[Tt * 32];
    __shared__ float  rg_s[Tt * Tt];
    __shared__ float4 p4_s[8][32];
    __shared__ int    pk_s[8][32];
    int tid = threadIdx.x;              // 256 = 8 warps = 8 nodes
    if (tid < 128) vg2_s[tid] = ((const float2*)g_vg[1])[tid];
    if (tid < Tt * Tt) rg_s[tid] = g_rg[1][tid];
    // re-zero deg histogram + scan flags for the next graph replay
    if (blockIdx.x < 64) {
        g_deg[blockIdx.x * 256 + tid] = 0;
        if (blockIdx.x == 0 && tid < 16) g_bflag[tid] = 0;
    }
    __syncthreads();
    int w = tid >> 5, lane = tid & 31;
    int n = blockIdx.x * 8 + w;
    int beg = g_off[n], end = g_off[n + 1];
    const float4* sj4p = (const float4*)g_sj1;
    float2 a0 = make_float2(0.f, 0.f), a1 = a0, a2 = a0, a3 = a0;
    float s0 = 0.f, s1 = 0.f, s2 = 0.f, s3 = 0.f;

    int pkbuf = (beg + lane < end) ? g_ect[beg + lane] : 0;
    for (int base = beg; base < end; base += 32) {
        int cnt = min(32, end - base);
        int pk = pkbuf;
        if (base + 32 + lane < end) pkbuf = g_ect[base + 32 + lane];
        float p0 = 0.f, p1 = 0.f, p2 = 0.f, p3 = 0.f;
        if (lane < cnt) {
            float4 sj4 = sj4p[pk & 16383];
            const float* rgc = rg_s + (pk >> 14);
            p0 = __expf(rgc[0]  + sj4.x);
            p1 = __expf(rgc[4]  + sj4.y);
            p2 = __expf(rgc[8]  + sj4.z);
            p3 = __expf(rgc[12] + sj4.w);
        }
        s0 += p0; s1 += p1; s2 += p2; s3 += p3;
        p4_s[w][lane] = make_float4(p0, p1, p2, p3);
        pk_s[w][lane] = pk;
        __syncwarp();
#pragma unroll 4
        for (int i = 0; i < cnt; i++) {
            float4 p = p4_s[w][i];
            int pki = pk_s[w][i];
            int ci = pki & 16383, tyi = pki >> 14;
            const float2* hp = (const float2*)(g_hw1 + (size_t)ci * (Tt * Dd));
            float2 v = vg2_s[tyi * 32 + lane];
            float2 h0 = hp[lane], h1 = hp[32 + lane], h2 = hp[64 + lane], h3 = hp[96 + lane];
            a0.x += p.x * v.x * h0.x; a0.y += p.x * v.y * h0.y;
            a1.x += p.y * v.x * h1.x; a1.y += p.y * v.y * h1.y;
            a2.x += p.z * v.x * h2.x; a2.y += p.z * v.y * h2.y;
            a3.x += p.w * v.x * h3.x; a3.y += p.w * v.y * h3.y;
        }
        __syncwarp();
    }
#pragma unroll
    for (int o = 16; o; o >>= 1) {
        s0 += __shfl_xor_sync(0xffffffffu, s0, o);
        s1 += __shfl_xor_sync(0xffffffffu, s1, o);
        s2 += __shfl_xor_sync(0xffffffffu, s2, o);
        s3 += __shfl_xor_sync(0xffffffffu, s3, o);
    }
    float2 acc[Tt] = {a0, a1, a2, a3};
    float ss[Tt] = {s0, s1, s2, s3};
#pragma unroll
    for (int t = 0; t < Tt; t++) {
        float inv = ss[t] > 0.f ? 1.f / ss[t] : 0.f;
        float2 o2 = make_float2(acc[t].x * inv, acc[t].y * inv);
        ((float2*)(out + (size_t)t * (Nn * Dd) + (size_t)n * Dd))[lane] = o2;
    }
}

extern "C" void kernel_launch(void* const* d_in, const int* in_sizes, int n_in,
                              void* d_out, int out_size) {
    const float* x     = (const float*)d_in[0];
    const float* ef0   = (const float*)d_in[1];
    const float* theta = (const float*)d_in[2];
    const float* wr    = (const float*)d_in[3];
    const float* we    = (const float*)d_in[4];
    const void*  eidx  = d_in[5];
    const void*  etyp  = d_in[6];
    float* out = (float*)d_out;

    k_hist<<<Ee / 1024, 256>>>(eidx, etyp);
    k_mid<<<16 + 1 + Nn / 32, 256>>>(x, ef0, we, theta, wr);
    k_scatter<<<Ee / 2048, 256>>>();
    k_fused0<<<Nn / 8, 256>>>(theta, we);
    k_fused1<<<Nn / 8, 256>>>(out);
}

// round 16
// speedup vs baseline: 1.2160x; 1.0473x over previous
#include <cuda_runtime.h>
#include <cuda_fp16.h>
#include <math.h>

#define Nn 16384
#define Ee 262144
#define Tt 4
#define Dd 64
#define TND (Tt*Nn*Dd)

// ---- scratch (zero-initialized at load; fused1 re-zeros deg/flags each run) ----
__device__ int    g_rr[Ee];            // packed (row | rank<<14)
__device__ int    g_cet[Ee];           // raw packed (col | ty<<14)
__device__ int    g_ect[Ee];           // CSR-sorted packed
__device__ int    g_deg[Nn], g_off[Nn + 1];
__device__ int    g_bval[16], g_bflag[16];
__device__ float  g_hw0[Nn * Dd];      // x @ we0 (single plane, fp32)
__device__ __half g_hw1h[TND];         // h1 @ we1, INTERLEAVED [n][t][d], fp16
__device__ float  g_sj0[Nn * Tt];      // interleaved [n][t]
__device__ float  g_sj1[Nn * Tt];
__device__ float  g_rg[2][Tt * Tt];
__device__ float  g_vg[2][Tt * Dd];

// ---- hist: per-thread dtype detect + degree count ----
__global__ void k_hist(const void* __restrict__ eidx, const void* __restrict__ etyp) {
    int i = blockIdx.x * blockDim.x + threadIdx.x;   // Ee/4 threads
    const long long* p = (const long long*)eidx;
    long long d0 = p[4 * i], d1 = p[4 * i + 1], d2 = p[4 * i + 2], d3 = p[4 * i + 3];
    bool is64 = ((unsigned long long)(d0 | d1 | d2 | d3)) < (unsigned long long)Nn;
    int4 rv, cv, tv;
    if (is64) {
        const long long* q = (const long long*)etyp;
        rv = make_int4((int)d0, (int)d1, (int)d2, (int)d3);
        int e = i * 4;
        cv = make_int4((int)p[Ee + e], (int)p[Ee + e + 1], (int)p[Ee + e + 2], (int)p[Ee + e + 3]);
        tv = make_int4((int)q[e], (int)q[e + 1], (int)q[e + 2], (int)q[e + 3]);
    } else {
        rv = ((const int4*)eidx)[i];
        cv = ((const int4*)eidx)[Ee / 4 + i];
        tv = ((const int4*)etyp)[i];
    }
    int4 rr, ce;
    rr.x = rv.x | (atomicAdd(&g_deg[rv.x], 1) << 14);
    rr.y = rv.y | (atomicAdd(&g_deg[rv.y], 1) << 14);
    rr.z = rv.z | (atomicAdd(&g_deg[rv.z], 1) << 14);
    rr.w = rv.w | (atomicAdd(&g_deg[rv.w], 1) << 14);
    ce.x = cv.x | (tv.x << 14);
    ce.y = cv.y | (tv.y << 14);
    ce.z = cv.z | (tv.z << 14);
    ce.w = cv.w | (tv.w << 14);
    ((int4*)g_rr)[i]  = rr;
    ((int4*)g_cet)[i] = ce;
}

// ---- rgef for BOTH layers ----
__device__ void rgef_body(const float* __restrict__ ef0, const float* __restrict__ theta,
                          const float* __restrict__ wr) {
    __shared__ float efa[Tt * Dd], efb[Tt * Dd];
    int tid = threadIdx.x;              // 256
    int t = tid >> 6, d = tid & 63;
    efa[tid] = ef0[tid];
    __syncthreads();
    if (tid < Tt * Tt) {
        int t1 = tid >> 2, t2 = tid & 3;
        const float* tg = theta + t1 * 3 * Dd;
        float s = 0.f;
#pragma unroll
        for (int k = 0; k < Dd; k++) s += tg[k] * efa[t2 * Dd + k];
        g_rg[0][tid] = s;
    }
    {
        float s = 0.f;
#pragma unroll
        for (int k = 0; k < Dd; k++) s += efa[t * Dd + k] * wr[k * Dd + d];
        g_vg[0][tid] = 1.f / (1.f + __expf(-s));
        efb[tid] = fmaxf(s, 0.f);
    }
    __syncthreads();
    if (tid < Tt * Tt) {
        int t1 = tid >> 2, t2 = tid & 3;
        const float* tg = theta + (Tt * 3 * Dd) + t1 * 3 * Dd;
        float s = 0.f;
#pragma unroll
        for (int k = 0; k < Dd; k++) s += tg[k] * efb[t2 * Dd + k];
        g_rg[1][tid] = s;
    }
    {
        const float* w1 = wr + Dd * Dd;
        float s = 0.f;
#pragma unroll
        for (int k = 0; k < Dd; k++) s += efb[t * Dd + k] * w1[k * Dd + d];
        g_vg[1][tid] = 1.f / (1.f + __expf(-s));
    }
}

// ---- scan body: 256 threads x int4, decoupled lookback (blocks 0..15) ----
__device__ void scan_body(int b) {
    __shared__ int sh[256];
    __shared__ int base_s;
    int tid = threadIdx.x;
    int i4 = b * 256 + tid;
    int4 v = ((const int4*)g_deg)[i4];
    int lsum = v.x + v.y + v.z + v.w;
    sh[tid] = lsum;
    __syncthreads();
    for (int off = 1; off < 256; off <<= 1) {
        int u = (tid >= off) ? sh[tid - off] : 0;
        __syncthreads();
        sh[tid] += u;
        __syncthreads();
    }
    if (tid == 255) {
        g_bval[b] = sh[255];
        __threadfence();
        atomicExch(&g_bflag[b], 1);
    }
    if (tid == 0) {
        int acc = 0;
        for (int j = 0; j < b; j++) {
            while (atomicAdd(&g_bflag[j], 0) == 0) { }
            acc += g_bval[j];
        }
        base_s = acc;
    }
    __syncthreads();
    int o = base_s + sh[tid] - lsum;
    int4 off4;
    off4.x = o;
    off4.y = o + v.x;
    off4.z = o + v.x + v.y;
    off4.w = o + v.x + v.y + v.z;
    ((int4*)g_off)[i4] = off4;
    if (b == 15 && tid == 255) g_off[Nn] = Ee;
}

// ---- gemm0 body: hw0 = x @ we0 + sj0 (blocks 17..) ----
__device__ void gemm0_body(int blk, const float* __restrict__ x,
                           const float* __restrict__ we, const float* __restrict__ theta) {
    __shared__ float we_s[Dd * Dd];
    __shared__ float h_s[32 * Dd];
    __shared__ float thj_s[Tt * Dd];
    int tid = threadIdx.x;              // 256
    int n0 = blk * 32;
#pragma unroll
    for (int i = 0; i < 16; i++) we_s[tid + i * 256] = we[tid + i * 256];
    const float* hb = x + (size_t)n0 * Dd;
#pragma unroll
    for (int i = 0; i < 8; i++) h_s[tid + i * 256] = hb[tid + i * 256];
    {
        int t = tid >> 6, d = tid & 63;
        thj_s[t * Dd + d] = theta[t * 3 * Dd + 2 * Dd + d];
    }
    __syncthreads();
    int d = tid & 63, ng = tid >> 6;
    float acc[8] = {0.f, 0.f, 0.f, 0.f, 0.f, 0.f, 0.f, 0.f};
#pragma unroll
    for (int k = 0; k < Dd; k++) {
        float wv = we_s[k * Dd + d];
#pragma unroll
        for (int j = 0; j < 8; j++) acc[j] += h_s[(ng * 8 + j) * Dd + k] * wv;
    }
    float* ob = g_hw0 + (size_t)n0 * Dd;
#pragma unroll
    for (int j = 0; j < 8; j++) ob[(ng * 8 + j) * Dd + d] = acc[j];

    int wid = tid >> 5, lane = tid & 31;
#pragma unroll
    for (int j = 0; j < 4; j++) {
        int nl = wid * 4 + j;
        float a = h_s[nl * Dd + lane], b = h_s[nl * Dd + lane + 32];
#pragma unroll
        for (int t = 0; t < Tt; t++) {
            float sj = a * thj_s[t * Dd + lane] + b * thj_s[t * Dd + lane + 32];
#pragma unroll
            for (int o = 16; o; o >>= 1) sj += __shfl_down_sync(0xffffffffu, sj, o);
            if (lane == 0) g_sj0[(n0 + nl) * Tt + t] = sj;
        }
    }
}

// ---- mid: scan (0..15) | rgef (16) | gemm0 (17..) ----
__global__ void k_mid(const float* __restrict__ x, const float* __restrict__ ef0,
                      const float* __restrict__ we, const float* __restrict__ theta,
                      const float* __restrict__ wr) {
    int b = blockIdx.x;
    if (b < 16) { scan_body(b); return; }
    if (b == 16) { rgef_body(ef0, theta, wr); return; }
    gemm0_body(b - 17, x, we, theta);
}

// ---- scatter: atomic-free, 8 edges/thread ----
__global__ void k_scatter() {
    int i = blockIdx.x * blockDim.x + threadIdx.x;
    int4 r0 = ((const int4*)g_rr)[2 * i];
    int4 r1 = ((const int4*)g_rr)[2 * i + 1];
    int4 c0 = ((const int4*)g_cet)[2 * i];
    int4 c1 = ((const int4*)g_cet)[2 * i + 1];
    int p0 = g_off[r0.x & 16383] + (((unsigned)r0.x) >> 14);
    int p1 = g_off[r0.y & 16383] + (((unsigned)r0.y) >> 14);
    int p2 = g_off[r0.z & 16383] + (((unsigned)r0.z) >> 14);
    int p3 = g_off[r0.w & 16383] + (((unsigned)r0.w) >> 14);
    int p4 = g_off[r1.x & 16383] + (((unsigned)r1.x) >> 14);
    int p5 = g_off[r1.y & 16383] + (((unsigned)r1.y) >> 14);
    int p6 = g_off[r1.z & 16383] + (((unsigned)r1.z) >> 14);
    int p7 = g_off[r1.w & 16383] + (((unsigned)r1.w) >> 14);
    g_ect[p0] = c0.x; g_ect[p1] = c0.y; g_ect[p2] = c0.z; g_ect[p3] = c0.w;
    g_ect[p4] = c1.x; g_ect[p5] = c1.y; g_ect[p6] = c1.z; g_ect[p7] = c1.w;
}

// ---- fused layer 0: warp per NODE; epilogue = h1->shared, sj1, then
//      BLOCK-WIDE hw1 GEMM (32 rows = 8 nodes x 4 t), fp16 hw1 store ----
__global__ void k_fused0(const float* __restrict__ theta, const float* __restrict__ we) {
    __shared__ float2 vg2_s[Tt * 32];
    __shared__ float  rg_s[Tt * Tt];
    __shared__ float2 thj1_2[Tt * 32];
    __shared__ float4 p4_s[8][32];
    __shared__ int    pk_s[8][32];
    __shared__ float  we1_s[Dd * Dd];     // 16KB
    __shared__ float  h_all[32 * Dd];     // 8KB: row = nodeLocal*4 + t
    int tid = threadIdx.x;              // 256 = 8 warps = 8 nodes
    if (tid < 128) vg2_s[tid] = ((const float2*)g_vg[0])[tid];
    else {
        int j = tid - 128;
        thj1_2[j] = make_float2(
            theta[(Tt * 3 * Dd) + (j >> 5) * 3 * Dd + 2 * Dd + (j & 31) * 2],
            theta[(Tt * 3 * Dd) + (j >> 5) * 3 * Dd + 2 * Dd + (j & 31) * 2 + 1]);
    }
    if (tid < Tt * Tt) rg_s[tid] = g_rg[0][tid];
    const float* w1 = we + Dd * Dd;
#pragma unroll
    for (int i = 0; i < 16; i++) we1_s[tid + i * 256] = w1[tid + i * 256];
    __syncthreads();
    int w = tid >> 5, lane = tid & 31;
    int n = blockIdx.x * 8 + w;
    int beg = g_off[n], end = g_off[n + 1];
    const float4* sj4p = (const float4*)g_sj0;
    float2 a0 = make_float2(0.f, 0.f), a1 = a0, a2 = a0, a3 = a0;
    float s0 = 0.f, s1 = 0.f, s2 = 0.f, s3 = 0.f;

    int pkbuf = (beg + lane < end) ? g_ect[beg + lane] : 0;
    for (int base = beg; base < end; base += 32) {
        int cnt = min(32, end - base);
        int pk = pkbuf;
        if (base + 32 + lane < end) pkbuf = g_ect[base + 32 + lane];
        float p0 = 0.f, p1 = 0.f, p2 = 0.f, p3 = 0.f;
        if (lane < cnt) {
            float4 sj4 = sj4p[pk & 16383];
            const float* rgc = rg_s + (pk >> 14);
            p0 = __expf(rgc[0]  + sj4.x);
            p1 = __expf(rgc[4]  + sj4.y);
            p2 = __expf(rgc[8]  + sj4.z);
            p3 = __expf(rgc[12] + sj4.w);
        }
        s0 += p0; s1 += p1; s2 += p2; s3 += p3;
        p4_s[w][lane] = make_float4(p0, p1, p2, p3);
        pk_s[w][lane] = pk;
        __syncwarp();
#pragma unroll 4
        for (int i = 0; i < cnt; i++) {
            float4 p = p4_s[w][i];
            int pki = pk_s[w][i];
            int ci = pki & 16383, tyi = pki >> 14;
            float2 h = ((const float2*)(g_hw0 + (size_t)ci * Dd))[lane];
            float2 v = vg2_s[tyi * 32 + lane];
            float vx = v.x * h.x, vy = v.y * h.y;
            a0.x += p.x * vx; a0.y += p.x * vy;
            a1.x += p.y * vx; a1.y += p.y * vy;
            a2.x += p.z * vx; a2.y += p.z * vy;
            a3.x += p.w * vx; a3.y += p.w * vy;
        }
        __syncwarp();
    }
#pragma unroll
    for (int o = 16; o; o >>= 1) {
        s0 += __shfl_xor_sync(0xffffffffu, s0, o);
        s1 += __shfl_xor_sync(0xffffffffu, s1, o);
        s2 += __shfl_xor_sync(0xffffffffu, s2, o);
        s3 += __shfl_xor_sync(0xffffffffu, s3, o);
    }

    float2 acc[Tt] = {a0, a1, a2, a3};
    float ss[Tt] = {s0, s1, s2, s3};
#pragma unroll
    for (int t = 0; t < Tt; t++) {
        float inv = ss[t] > 0.f ? 1.f / ss[t] : 0.f;
        float v0 = fmaxf(acc[t].x * inv, 0.f);
        float v1 = fmaxf(acc[t].y * inv, 0.f);
        int row = w * 4 + t;
        h_all[row * Dd + 2 * lane]     = v0;
        h_all[row * Dd + 2 * lane + 1] = v1;
        float2 tj = thj1_2[t * 32 + lane];
        float sj = v0 * tj.x + v1 * tj.y;
#pragma unroll
        for (int o = 16; o; o >>= 1) sj += __shfl_down_sync(0xffffffffu, sj, o);
        if (lane == 0) g_sj1[n * Tt + t] = sj;
    }
    __syncthreads();

    // block-wide GEMM: hw1[rows 0..31] = h_all @ we1, stored fp16
    int d = tid & 63, ng = tid >> 6;
    float gacc[8] = {0.f, 0.f, 0.f, 0.f, 0.f, 0.f, 0.f, 0.f};
#pragma unroll
    for (int k = 0; k < Dd; k++) {
        float wv = we1_s[k * Dd + d];
#pragma unroll
        for (int j = 0; j < 8; j++) gacc[j] += h_all[(ng * 8 + j) * Dd + k] * wv;
    }
    size_t ob = ((size_t)blockIdx.x * 8) * (Tt * Dd);   // rows map directly: [n][t][d]
#pragma unroll
    for (int j = 0; j < 8; j++)
        g_hw1h[ob + (size_t)(ng * 8 + j) * Dd + d] = __float2half(gacc[j]);
}

// ---- fused layer 1: warp per NODE, fp16 hw1 gather (512B/edge) ----
__global__ void k_fused1(float* __restrict__ out) {
    __shared__ float2 vg2_s[Tt * 32];
    __shared__ float  rg_s[Tt * Tt];
    __shared__ float4 p4_s[8][32];
    __shared__ int    pk_s[8][32];
    int tid = threadIdx.x;              // 256 = 8 warps = 8 nodes
    if (tid < 128) vg2_s[tid] = ((const float2*)g_vg[1])[tid];
    if (tid < Tt * Tt) rg_s[tid] = g_rg[1][tid];
    // re-zero deg histogram + scan flags for the next graph replay
    if (blockIdx.x < 64) {
        g_deg[blockIdx.x * 256 + tid] = 0;
        if (blockIdx.x == 0 && tid < 16) g_bflag[tid] = 0;
    }
    __syncthreads();
    int w = tid >> 5, lane = tid & 31;
    int n = blockIdx.x * 8 + w;
    int beg = g_off[n], end = g_off[n + 1];
    const float4* sj4p = (const float4*)g_sj1;
    float2 a0 = make_float2(0.f, 0.f), a1 = a0, a2 = a0, a3 = a0;
    float s0 = 0.f, s1 = 0.f, s2 = 0.f, s3 = 0.f;

    int pkbuf = (beg + lane < end) ? g_ect[beg + lane] : 0;
    for (int base = beg; base < end; base += 32) {
        int cnt = min(32, end - base);
        int pk = pkbuf;
        if (base + 32 + lane < end) pkbuf = g_ect[base + 32 + lane];
        float p0 = 0.f, p1 = 0.f, p2 = 0.f, p3 = 0.f;
        if (lane < cnt) {
            float4 sj4 = sj4p[pk & 16383];
            const float* rgc = rg_s + (pk >> 14);
            p0 = __expf(rgc[0]  + sj4.x);
            p1 = __expf(rgc[4]  + sj4.y);
            p2 = __expf(rgc[8]  + sj4.z);
            p3 = __expf(rgc[12] + sj4.w);
        }
        s0 += p0; s1 += p1; s2 += p2; s3 += p3;
        p4_s[w][lane] = make_float4(p0, p1, p2, p3);
        pk_s[w][lane] = pk;
        __syncwarp();
#pragma unroll 4
        for (int i = 0; i < cnt; i++) {
            float4 p = p4_s[w][i];
            int pki = pk_s[w][i];
            int ci = pki & 16383, tyi = pki >> 14;
            const __half2* hp = (const __half2*)(g_hw1h + (size_t)ci * (Tt * Dd));
            float2 v = vg2_s[tyi * 32 + lane];
            float2 h0 = __half22float2(hp[lane]);
            float2 h1 = __half22float2(hp[32 + lane]);
            float2 h2 = __half22float2(hp[64 + lane]);
            float2 h3 = __half22float2(hp[96 + lane]);
            a0.x += p.x * v.x * h0.x; a0.y += p.x * v.y * h0.y;
            a1.x += p.y * v.x * h1.x; a1.y += p.y * v.y * h1.y;
            a2.x += p.z * v.x * h2.x; a2.y += p.z * v.y * h2.y;
            a3.x += p.w * v.x * h3.x; a3.y += p.w * v.y * h3.y;
        }
        __syncwarp();
    }
#pragma unroll
    for (int o = 16; o; o >>= 1) {
        s0 += __shfl_xor_sync(0xffffffffu, s0, o);
        s1 += __shfl_xor_sync(0xffffffffu, s1, o);
        s2 += __shfl_xor_sync(0xffffffffu, s2, o);
        s3 += __shfl_xor_sync(0xffffffffu, s3, o);
    }
    float2 acc[Tt] = {a0, a1, a2, a3};
    float ss[Tt] = {s0, s1, s2, s3};
#pragma unroll
    for (int t = 0; t < Tt; t++) {
        float inv = ss[t] > 0.f ? 1.f / ss[t] : 0.f;
        float2 o2 = make_float2(acc[t].x * inv, acc[t].y * inv);
        ((float2*)(out + (size_t)t * (Nn * Dd) + (size_t)n * Dd))[lane] = o2;
    }
}

extern "C" void kernel_launch(void* const* d_in, const int* in_sizes, int n_in,
                              void* d_out, int out_size) {
    const float* x     = (const float*)d_in[0];
    const float* ef0   = (const float*)d_in[1];
    const float* theta = (const float*)d_in[2];
    const float* wr    = (const float*)d_in[3];
    const float* we    = (const float*)d_in[4];
    const void*  eidx  = d_in[5];
    const void*  etyp  = d_in[6];
    float* out = (float*)d_out;

    k_hist<<<Ee / 1024, 256>>>(eidx, etyp);
    k_mid<<<16 + 1 + Nn / 32, 256>>>(x, ef0, we, theta, wr);
    k_scatter<<<Ee / 2048, 256>>>();
    k_fused0<<<Nn / 8, 256>>>(theta, we);
    k_fused1<<<Nn / 8, 256>>>(out);
}